// round 3
// baseline (speedup 1.0000x reference)
#include <cuda_runtime.h>
#include <cuda_bf16.h>
#include <cstdint>

// LinearMultiheadSplit: out[n] = x[n] @ (W[head] + 0.1*D[head*4+split]) + bias[head]
// N=1024 samples, IN=OUT=512, 32 heads, 4 splits -> 128 combos.
//
// Strategy: group samples by (head,split) combo. One block per (combo, 128-col tile).
// Each block reads its W/D column-stripe from DRAM exactly once and reuses it across
// all samples of the combo (packed f32x2 accumulators, 2 samples per 64-bit lane,
// via PTX fma.rn.f32x2 -- double the fp32 FMA rate vs scalar FFMA on sm_103a).

#define N_SAMPLES 1024
#define IN_F      512
#define OUT_F     512
#define N_HEADS   32
#define N_SPLITS  4
#define N_COMBO   (N_HEADS * N_SPLITS)
#define COLS_PER_BLOCK 128
#define THREADS   128
#define CHUNK     16   // samples per smem x-tile

__device__ __forceinline__ unsigned long long dup2(float v) {
    unsigned long long r;
    unsigned u = __float_as_uint(v);
    asm("mov.b64 %0, {%1, %1};" : "=l"(r) : "r"(u));
    return r;
}

__device__ __forceinline__ unsigned long long fma2(unsigned long long a,
                                                   unsigned long long b,
                                                   unsigned long long c) {
    unsigned long long d;
    asm("fma.rn.f32x2 %0, %1, %2, %3;" : "=l"(d) : "l"(a), "l"(b), "l"(c));
    return d;
}

__device__ __forceinline__ void unpack2(unsigned long long v, float& lo, float& hi) {
    unsigned a, b;
    asm("mov.b64 {%0, %1}, %2;" : "=r"(a), "=r"(b) : "l"(v));
    lo = __uint_as_float(a);
    hi = __uint_as_float(b);
}

// Inner loop over k for one chunk, with PAIRS sample-pairs live (PAIRS in {1,2,4,8}).
// xs smem layout: xs[k][s], s = 0..15, row stride 16 floats (64 B, 16B-aligned rows).
// All threads read the same xs address per k -> pure broadcast, conflict-free.
template <int PAIRS>
__device__ __forceinline__ void chunk_compute(
    const float* __restrict__ Wp, const float* __restrict__ Dp,
    unsigned xs_addr, const short* s_list, int base, int m,
    int c, float bval, float* __restrict__ out)
{
    unsigned long long acc[PAIRS];
#pragma unroll
    for (int p = 0; p < PAIRS; ++p) acc[p] = 0ull;

#pragma unroll 4
    for (int k = 0; k < IN_F; ++k) {
        float w = __ldg(Wp + (size_t)k * OUT_F);
        float d = __ldg(Dp + (size_t)k * OUT_F);
        float wv = fmaf(d, 0.1f, w);            // imm-form FFMA (rt 1)
        unsigned long long wv2 = dup2(wv);      // one pack per k, not per sample

        unsigned a = xs_addr + (unsigned)k * (CHUNK * 4u);
        unsigned long long xp[PAIRS];
        if (PAIRS == 1) {
            asm volatile("ld.shared.b64 %0, [%1];" : "=l"(xp[0]) : "r"(a));
        } else {
#pragma unroll
            for (int p = 0; p < PAIRS; p += 2) {
                asm volatile("ld.shared.v2.b64 {%0, %1}, [%2];"
                             : "=l"(xp[p]), "=l"(xp[p + 1])
                             : "r"(a + (unsigned)(8 * p)));
            }
        }
#pragma unroll
        for (int p = 0; p < PAIRS; ++p) acc[p] = fma2(xp[p], wv2, acc[p]);
    }

#pragma unroll
    for (int p = 0; p < PAIRS; ++p) {
        float lo, hi;
        unpack2(acc[p], lo, hi);
        int i0 = base + 2 * p;
        if (i0 < m) {
            out[(size_t)s_list[i0] * OUT_F + c] = lo + bval;
        }
        if (i0 + 1 < m) {
            out[(size_t)s_list[i0 + 1] * OUT_F + c] = hi + bval;
        }
    }
}

__global__ void __launch_bounds__(THREADS)
lms_kernel(const float* __restrict__ X,
           const int* __restrict__ hix,
           const int* __restrict__ six,
           const float* __restrict__ W,
           const float* __restrict__ D,
           const float* __restrict__ B,
           float* __restrict__ out)
{
    __shared__ int   s_cnt;
    __shared__ short s_list[N_SAMPLES];
    __shared__ __align__(16) float xs[IN_F * CHUNK];  // 32 KB, transposed x: xs[k][s]

    const int tid = threadIdx.x;
    const int g   = blockIdx.y;          // combo 0..127
    const int c   = blockIdx.x * COLS_PER_BLOCK + tid;  // output column
    const int h   = g >> 2;
    const int sp  = g & 3;

    // ---- Phase A: build sample list for this combo (scan is L2-resident, trivial) ----
    if (tid == 0) s_cnt = 0;
    __syncthreads();
    for (int n = tid; n < N_SAMPLES; n += THREADS) {
        if (hix[n] == h && six[n] == sp) {
            int p = atomicAdd(&s_cnt, 1);
            s_list[p] = (short)n;
        }
    }
    __syncthreads();
    const int m = s_cnt;
    if (m == 0) return;   // uniform across block

    const float* Wp = W + (size_t)h * (IN_F * OUT_F) + c;
    const float* Dp = D + (size_t)g * (IN_F * OUT_F) + c;
    const float  bval = B[h * OUT_F + c];
    const unsigned xs_addr = (unsigned)__cvta_generic_to_shared(xs);

    // Loader mapping: s = tid & 15 (sample slot), jj = tid >> 4 (k-range)
    const int s  = tid & 15;
    const int jj = tid >> 4;             // 0..7, each covers 64 k-values

    for (int base = 0; base < m; base += CHUNK) {
        // ---- stage transposed x chunk into smem (zero-padded) ----
        const int  sg    = base + s;
        const bool valid = sg < m;
        const float4* xrow =
            valid ? (const float4*)(X + (size_t)s_list[sg] * IN_F) : (const float4*)X;
#pragma unroll
        for (int i = 0; i < 16; ++i) {
            int q  = jj * 16 + i;        // float4 index 0..127 -> k0 = 4q
            float4 v = valid ? __ldg(&xrow[q]) : make_float4(0.f, 0.f, 0.f, 0.f);
            int k0 = q * 4;
            xs[(k0 + 0) * CHUNK + s] = v.x;
            xs[(k0 + 1) * CHUNK + s] = v.y;
            xs[(k0 + 2) * CHUNK + s] = v.z;
            xs[(k0 + 3) * CHUNK + s] = v.w;
        }
        __syncthreads();

        int mc = m - base;
        if (mc > CHUNK) mc = CHUNK;

        if (mc > 8)      chunk_compute<8>(Wp, Dp, xs_addr, s_list, base, m, c, bval, out);
        else if (mc > 4) chunk_compute<4>(Wp, Dp, xs_addr, s_list, base, m, c, bval, out);
        else if (mc > 2) chunk_compute<2>(Wp, Dp, xs_addr, s_list, base, m, c, bval, out);
        else             chunk_compute<1>(Wp, Dp, xs_addr, s_list, base, m, c, bval, out);

        __syncthreads();   // before next chunk overwrites xs
    }
}

extern "C" void kernel_launch(void* const* d_in, const int* in_sizes, int n_in,
                              void* d_out, int out_size)
{
    const float* X   = (const float*)d_in[0];
    const int*   hix = (const int*)d_in[1];
    const int*   six = (const int*)d_in[2];
    const float* W   = (const float*)d_in[3];
    const float* D   = (const float*)d_in[4];
    const float* B   = (const float*)d_in[5];
    float*       out = (float*)d_out;

    dim3 grid(OUT_F / COLS_PER_BLOCK, N_COMBO);   // (4, 128) = 512 blocks
    lms_kernel<<<grid, THREADS>>>(X, hix, six, W, D, B, out);
}

// round 7
// speedup vs baseline: 1.1973x; 1.1973x over previous
#include <cuda_runtime.h>
#include <cuda_bf16.h>
#include <cstdint>

// LinearMultiheadSplit: out[n] = x[n] @ (W[head] + 0.1*D[head*4+split]) + bias[head]
// N=1024, IN=OUT=512, 32 heads x 4 splits -> 128 combos.
//
// v4: latency-bound fix. Block = 256 threads = 2 k-groups x 128 threads.
//  - thread owns 2 columns (float2 LDG.64, 256B/warp coalesced)
//  - k split in-block: group 0 does k[0,256), group 1 k[256,512); smem reduce
//  - explicit depth-4 software pipeline on W/D loads (8-16 LDGs in flight/thread)
//  - packed fma.rn.f32x2: 2 samples per 64-bit lane
// Grid = 2 col-tiles x 128 combos = 256 blocks. Deterministic, no atomics to gmem.

#define N_SAMPLES 1024
#define IN_F      512
#define OUT_F     512
#define N_HEADS   32
#define N_SPLITS  4
#define N_COMBO   (N_HEADS * N_SPLITS)
#define THREADS   256
#define KHALF     256          // k per group
#define COLS_PER_BLOCK 256     // 128 threads * 2 cols
#define CHUNK     8            // samples per tile (4 f32x2 pairs)
#define PIPE      4            // software pipeline depth
#define ROWF2     (OUT_F / 2)  // float2 per k-row = 256

__device__ __forceinline__ unsigned long long dup2(float v) {
    unsigned long long r; unsigned u = __float_as_uint(v);
    asm("mov.b64 %0, {%1, %1};" : "=l"(r) : "r"(u));
    return r;
}
__device__ __forceinline__ unsigned long long fma2(unsigned long long a,
                                                   unsigned long long b,
                                                   unsigned long long c) {
    unsigned long long d;
    asm("fma.rn.f32x2 %0, %1, %2, %3;" : "=l"(d) : "l"(a), "l"(b), "l"(c));
    return d;
}
__device__ __forceinline__ void unpack2(unsigned long long v, float& lo, float& hi) {
    unsigned a, b;
    asm("mov.b64 {%0, %1}, %2;" : "=r"(a), "=r"(b) : "l"(v));
    lo = __uint_as_float(a); hi = __uint_as_float(b);
}

__global__ void __launch_bounds__(THREADS)
lms_kernel(const float* __restrict__ X,
           const int* __restrict__ hix,
           const int* __restrict__ six,
           const float* __restrict__ W,
           const float* __restrict__ D,
           const float* __restrict__ B,
           float* __restrict__ out)
{
    __shared__ int   s_cnt;
    __shared__ short s_list[N_SAMPLES];
    __shared__ __align__(16) float xs[IN_F * CHUNK];   // 16 KB, xs[k][s], row=32B
    __shared__ float red[16 * 128];                    // 8 KB, group-1 partials

    const int tid = threadIdx.x;
    const int g   = blockIdx.y;            // combo
    const int h   = g >> 2;
    const int sp  = g & 3;
    const int kg  = tid >> 7;              // k-group 0/1
    const int t   = tid & 127;
    const int c0  = blockIdx.x * COLS_PER_BLOCK + t * 2;

    // ---- Phase A: build sample list for this combo ----
    if (tid == 0) s_cnt = 0;
    __syncthreads();
    for (int n = tid; n < N_SAMPLES; n += THREADS) {
        if (hix[n] == h && six[n] == sp) {
            int p = atomicAdd(&s_cnt, 1);
            s_list[p] = (short)n;
        }
    }
    __syncthreads();
    const int m = s_cnt;
    if (m == 0) return;                    // uniform across block

    const float2* wp = (const float2*)(W + (size_t)h * (IN_F * OUT_F)
                                         + (size_t)(kg * KHALF) * OUT_F + c0);
    const float2* dp = (const float2*)(D + (size_t)g * (IN_F * OUT_F)
                                         + (size_t)(kg * KHALF) * OUT_F + c0);
    const float2  bv = *(const float2*)(B + h * OUT_F + c0);
    const unsigned xs_addr = (unsigned)__cvta_generic_to_shared(xs);
    const unsigned xa = xs_addr + (unsigned)(kg * KHALF * (CHUNK * 4));

    // staging mapping: s = tid&7 (sample slot), q0 = tid>>3 (float4 index base)
    const int s  = tid & 7;
    const int q0 = tid >> 3;               // 0..31

    for (int base = 0; base < m; base += CHUNK) {
        // ---- stage x chunk transposed into smem (zero-padded) ----
        const int  sg    = base + s;
        const bool valid = sg < m;
        const float4* xrow =
            valid ? (const float4*)(X + (size_t)s_list[sg] * IN_F) : (const float4*)X;
#pragma unroll
        for (int i = 0; i < 4; ++i) {
            int Q = q0 + i * 32;           // 0..127
            float4 v = valid ? __ldg(xrow + Q) : make_float4(0.f, 0.f, 0.f, 0.f);
            int k0 = Q * 4;
            xs[(k0 + 0) * CHUNK + s] = v.x;
            xs[(k0 + 1) * CHUNK + s] = v.y;
            xs[(k0 + 2) * CHUNK + s] = v.z;
            xs[(k0 + 3) * CHUNK + s] = v.w;
        }
        __syncthreads();

        // ---- pipelined k-loop over this group's k-half ----
        unsigned long long acc[8];         // [0..3]=col0 pairs, [4..7]=col1 pairs
#pragma unroll
        for (int j = 0; j < 8; ++j) acc[j] = 0ull;

        float2 wbuf[PIPE], dbuf[PIPE];
#pragma unroll
        for (int p = 0; p < PIPE; ++p) {
            wbuf[p] = __ldg(wp + p * ROWF2);
            dbuf[p] = __ldg(dp + p * ROWF2);
        }

#pragma unroll 1
        for (int kk = 0; kk < KHALF; kk += PIPE) {
#pragma unroll
            for (int p = 0; p < PIPE; ++p) {
                float2 w2 = wbuf[p];
                float2 d2 = dbuf[p];
                int kn  = kk + PIPE + p;
                int kpf = kn < KHALF ? kn : (KHALF - 1);   // clamp: stays in-slab
                wbuf[p] = __ldg(wp + (size_t)kpf * ROWF2);
                dbuf[p] = __ldg(dp + (size_t)kpf * ROWF2);

                float wv0 = fmaf(d2.x, 0.1f, w2.x);
                float wv1 = fmaf(d2.y, 0.1f, w2.y);
                unsigned long long wva = dup2(wv0);
                unsigned long long wvb = dup2(wv1);

                unsigned a = xa + (unsigned)((kk + p) * (CHUNK * 4));
                unsigned long long x0, x1, x2, x3;
                asm volatile("ld.shared.v2.b64 {%0,%1},[%2];"
                             : "=l"(x0), "=l"(x1) : "r"(a));
                asm volatile("ld.shared.v2.b64 {%0,%1},[%2];"
                             : "=l"(x2), "=l"(x3) : "r"(a + 16));

                acc[0] = fma2(x0, wva, acc[0]);
                acc[1] = fma2(x1, wva, acc[1]);
                acc[2] = fma2(x2, wva, acc[2]);
                acc[3] = fma2(x3, wva, acc[3]);
                acc[4] = fma2(x0, wvb, acc[4]);
                acc[5] = fma2(x1, wvb, acc[5]);
                acc[6] = fma2(x2, wvb, acc[6]);
                acc[7] = fma2(x3, wvb, acc[7]);
            }
        }

        // ---- reduce group 1 -> group 0, add bias, write out ----
        __syncthreads();                   // k-loops done, xs free, red writable
        if (kg == 1) {
#pragma unroll
            for (int j = 0; j < 8; ++j) {
                float lo, hi;
                unpack2(acc[j], lo, hi);
                red[(2 * j + 0) * 128 + t] = lo;
                red[(2 * j + 1) * 128 + t] = hi;
            }
        }
        __syncthreads();
        if (kg == 0) {
            float v0[CHUNK], v1[CHUNK];    // per-sample col0/col1
#pragma unroll
            for (int pr = 0; pr < 4; ++pr) {
                float lo, hi;
                unpack2(acc[pr], lo, hi);
                v0[2 * pr + 0] = lo + red[(2 * pr + 0) * 128 + t];
                v0[2 * pr + 1] = hi + red[(2 * pr + 1) * 128 + t];
                unpack2(acc[4 + pr], lo, hi);
                v1[2 * pr + 0] = lo + red[(2 * (4 + pr) + 0) * 128 + t];
                v1[2 * pr + 1] = hi + red[(2 * (4 + pr) + 1) * 128 + t];
            }
#pragma unroll
            for (int i = 0; i < CHUNK; ++i) {
                if (base + i < m) {
                    int n = s_list[base + i];
                    float2 o = make_float2(v0[i] + bv.x, v1[i] + bv.y);
                    *(float2*)(out + (size_t)n * OUT_F + c0) = o;
                }
            }
        }
        __syncthreads();                   // before next chunk restages xs / red
    }
}

extern "C" void kernel_launch(void* const* d_in, const int* in_sizes, int n_in,
                              void* d_out, int out_size)
{
    const float* X   = (const float*)d_in[0];
    const int*   hix = (const int*)d_in[1];
    const int*   six = (const int*)d_in[2];
    const float* W   = (const float*)d_in[3];
    const float* D   = (const float*)d_in[4];
    const float* B   = (const float*)d_in[5];
    float*       out = (float*)d_out;

    dim3 grid(OUT_F / COLS_PER_BLOCK, N_COMBO);   // (2, 128) = 256 blocks
    lms_kernel<<<grid, THREADS>>>(X, hix, six, W, D, B, out);
}

// round 8
// speedup vs baseline: 2.4178x; 2.0194x over previous
#include <cuda_runtime.h>
#include <cuda_bf16.h>
#include <cstdint>

// LinearMultiheadSplit: out[n] = x[n] @ (W[head] + 0.1*D[head*4+split]) + bias[head]
// N=1024, IN=OUT=512, 32 heads x 4 splits -> 128 combos.
//
// v5: traffic + latency fix.
//  - single k-pass per block (CHUNK=16, PAIRS template 4/8): W/D stripe read ONCE,
//    split-blocks of a head stream W in lockstep -> L2 serves 3 of 4 W reads
//  - depth-8 clamp-free software pipeline (16 LDG.64 in flight per thread)
//  - reduction smem aliased onto xs (dead after k-loop): 2 blocks/SM
//  - packed fma.rn.f32x2: 2 samples per 64-bit lane

#define N_SAMPLES 1024
#define IN_F      512
#define OUT_F     512
#define N_HEADS   32
#define N_SPLITS  4
#define N_COMBO   (N_HEADS * N_SPLITS)
#define THREADS   256
#define KHALF     256          // k per group (2 groups)
#define COLS_PER_BLOCK 256     // 128 threads * 2 cols
#define CHUNK     16           // samples per tile (8 f32x2 pairs max)
#define PIPE      8            // software pipeline depth
#define ROWF2     (OUT_F / 2)  // float2 per k-row = 256

__device__ __forceinline__ unsigned long long dup2(float v) {
    unsigned long long r; unsigned u = __float_as_uint(v);
    asm("mov.b64 %0, {%1, %1};" : "=l"(r) : "r"(u));
    return r;
}
__device__ __forceinline__ unsigned long long fma2(unsigned long long a,
                                                   unsigned long long b,
                                                   unsigned long long c) {
    unsigned long long d;
    asm("fma.rn.f32x2 %0, %1, %2, %3;" : "=l"(d) : "l"(a), "l"(b), "l"(c));
    return d;
}
__device__ __forceinline__ void unpack2(unsigned long long v, float& lo, float& hi) {
    unsigned a, b;
    asm("mov.b64 {%0, %1}, %2;" : "=r"(a), "=r"(b) : "l"(v));
    lo = __uint_as_float(a); hi = __uint_as_float(b);
}

// one k-step: combine W/D, broadcast-load PAIRS x-pairs from smem, accumulate
template <int PAIRS>
__device__ __forceinline__ void kstep(int k, float2 w2, float2 d2, unsigned xa,
                                      unsigned long long* acc)
{
    float wv0 = fmaf(d2.x, 0.1f, w2.x);
    float wv1 = fmaf(d2.y, 0.1f, w2.y);
    unsigned long long wva = dup2(wv0);
    unsigned long long wvb = dup2(wv1);

    unsigned a = xa + (unsigned)k * (CHUNK * 4);
    unsigned long long xp[PAIRS];
#pragma unroll
    for (int p = 0; p < PAIRS; p += 2) {
        asm volatile("ld.shared.v2.b64 {%0,%1},[%2];"
                     : "=l"(xp[p]), "=l"(xp[p + 1]) : "r"(a + (unsigned)(8 * p)));
    }
#pragma unroll
    for (int p = 0; p < PAIRS; ++p) {
        acc[p]         = fma2(xp[p], wva, acc[p]);
        acc[PAIRS + p] = fma2(xp[p], wvb, acc[PAIRS + p]);
    }
}

// full KHALF pass + cross-group reduce + store. All __syncthreads block-uniform.
template <int PAIRS>
__device__ __forceinline__ void compute_pass(
    const float2* __restrict__ wp, const float2* __restrict__ dp,
    unsigned xa, const short* __restrict__ s_list, int base, int mc,
    float2 bv, float* __restrict__ out, int c0, int kg, int t,
    float* __restrict__ red)
{
    unsigned long long acc[2 * PAIRS];
#pragma unroll
    for (int j = 0; j < 2 * PAIRS; ++j) acc[j] = 0ull;

    // prologue: fill pipeline
    float2 wbuf[PIPE], dbuf[PIPE];
#pragma unroll
    for (int p = 0; p < PIPE; ++p) {
        wbuf[p] = __ldg(wp + (size_t)p * ROWF2);
        dbuf[p] = __ldg(dp + (size_t)p * ROWF2);
    }

    // main: consume k=kk+p, prefetch k=kk+p+PIPE (always in-bounds, no clamp)
#pragma unroll 1
    for (int kk = 0; kk < KHALF - PIPE; kk += PIPE) {
#pragma unroll
        for (int p = 0; p < PIPE; ++p) {
            float2 w2 = wbuf[p], d2 = dbuf[p];
            wbuf[p] = __ldg(wp + (size_t)(kk + PIPE + p) * ROWF2);
            dbuf[p] = __ldg(dp + (size_t)(kk + PIPE + p) * ROWF2);
            kstep<PAIRS>(kk + p, w2, d2, xa, acc);
        }
    }
    // drain tail
#pragma unroll
    for (int p = 0; p < PIPE; ++p) {
        kstep<PAIRS>(KHALF - PIPE + p, wbuf[p], dbuf[p], xa, acc);
    }

    // ---- reduce group 1 -> group 0 via red (aliases xs; xs is dead now) ----
    __syncthreads();
    if (kg == 1) {
#pragma unroll
        for (int pr = 0; pr < PAIRS; ++pr) {
            float lo, hi;
            unpack2(acc[pr], lo, hi);
            red[(2 * pr + 0) * 128 + t] = lo;
            red[(2 * pr + 1) * 128 + t] = hi;
            unpack2(acc[PAIRS + pr], lo, hi);
            red[(2 * PAIRS + 2 * pr + 0) * 128 + t] = lo;
            red[(2 * PAIRS + 2 * pr + 1) * 128 + t] = hi;
        }
    }
    __syncthreads();
    if (kg == 0) {
        float v0[2 * PAIRS], v1[2 * PAIRS];
#pragma unroll
        for (int pr = 0; pr < PAIRS; ++pr) {
            float lo, hi;
            unpack2(acc[pr], lo, hi);
            v0[2 * pr + 0] = lo + red[(2 * pr + 0) * 128 + t];
            v0[2 * pr + 1] = hi + red[(2 * pr + 1) * 128 + t];
            unpack2(acc[PAIRS + pr], lo, hi);
            v1[2 * pr + 0] = lo + red[(2 * PAIRS + 2 * pr + 0) * 128 + t];
            v1[2 * pr + 1] = hi + red[(2 * PAIRS + 2 * pr + 1) * 128 + t];
        }
#pragma unroll
        for (int i = 0; i < 2 * PAIRS; ++i) {
            if (i < mc) {
                int n = s_list[base + i];
                float2 o = make_float2(v0[i] + bv.x, v1[i] + bv.y);
                *(float2*)(out + (size_t)n * OUT_F + c0) = o;
            }
        }
    }
}

__global__ void __launch_bounds__(THREADS, 2)
lms_kernel(const float* __restrict__ X,
           const int* __restrict__ hix,
           const int* __restrict__ six,
           const float* __restrict__ W,
           const float* __restrict__ D,
           const float* __restrict__ B,
           float* __restrict__ out)
{
    __shared__ int   s_cnt;
    __shared__ short s_list[N_SAMPLES];
    __shared__ __align__(16) float xs[IN_F * CHUNK];   // 32 KB; also reused as `red`

    const int tid = threadIdx.x;
    const int g   = blockIdx.y;            // combo
    const int h   = g >> 2;
    const int sp  = g & 3;
    const int kg  = tid >> 7;              // k-group 0/1
    const int t   = tid & 127;
    const int c0  = blockIdx.x * COLS_PER_BLOCK + t * 2;

    // ---- Phase A: build sample list for this combo ----
    if (tid == 0) s_cnt = 0;
    __syncthreads();
    for (int n = tid; n < N_SAMPLES; n += THREADS) {
        if (hix[n] == h && six[n] == sp) {
            int p = atomicAdd(&s_cnt, 1);
            s_list[p] = (short)n;
        }
    }
    __syncthreads();
    const int m = s_cnt;
    if (m == 0) return;                    // uniform across block

    const float2* wp = (const float2*)(W + (size_t)h * (IN_F * OUT_F)
                                         + (size_t)(kg * KHALF) * OUT_F + c0);
    const float2* dp = (const float2*)(D + (size_t)g * (IN_F * OUT_F)
                                         + (size_t)(kg * KHALF) * OUT_F + c0);
    const float2  bv = *(const float2*)(B + h * OUT_F + c0);
    const unsigned xs_addr = (unsigned)__cvta_generic_to_shared(xs);
    const unsigned xa = xs_addr + (unsigned)(kg * KHALF * (CHUNK * 4));

    // staging mapping: s = tid&15 (sample slot), q0 = tid>>4 (float4 base)
    const int s  = tid & 15;
    const int q0 = tid >> 4;               // 0..15

    // Nearly always a single pass (P[m>16] ~ 0.4% per combo).
    for (int base = 0; base < m; base += CHUNK) {
        // ---- stage x chunk transposed into smem (zero-padded) ----
        const int  sg    = base + s;
        const bool valid = sg < m;
        const float4* xrow =
            valid ? (const float4*)(X + (size_t)s_list[sg] * IN_F) : (const float4*)X;
#pragma unroll
        for (int i = 0; i < 8; ++i) {
            int Q = q0 + i * 16;           // 0..127
            float4 v = valid ? __ldg(xrow + Q) : make_float4(0.f, 0.f, 0.f, 0.f);
            int k0 = Q * 4;
            xs[(k0 + 0) * CHUNK + s] = v.x;
            xs[(k0 + 1) * CHUNK + s] = v.y;
            xs[(k0 + 2) * CHUNK + s] = v.z;
            xs[(k0 + 3) * CHUNK + s] = v.w;
        }
        __syncthreads();

        int mc = m - base;
        if (mc > CHUNK) mc = CHUNK;

        if (mc > 8) compute_pass<8>(wp, dp, xa, s_list, base, mc, bv, out, c0, kg, t, xs);
        else        compute_pass<4>(wp, dp, xa, s_list, base, mc, bv, out, c0, kg, t, xs);

        __syncthreads();                   // before next pass restages xs
    }
}

extern "C" void kernel_launch(void* const* d_in, const int* in_sizes, int n_in,
                              void* d_out, int out_size)
{
    const float* X   = (const float*)d_in[0];
    const int*   hix = (const int*)d_in[1];
    const int*   six = (const int*)d_in[2];
    const float* W   = (const float*)d_in[3];
    const float* D   = (const float*)d_in[4];
    const float* B   = (const float*)d_in[5];
    float*       out = (float*)d_out;

    dim3 grid(OUT_F / COLS_PER_BLOCK, N_COMBO);   // (2, 128) = 256 blocks
    lms_kernel<<<grid, THREADS>>>(X, hix, six, W, D, B, out);
}